// round 15
// baseline (speedup 1.0000x reference)
#include <cuda_runtime.h>

// Problem constants (match reference)
#define K_VOX 12000
#define T_PTS 35
#define F_IN  7
#define D_DIM 10
#define H_DIM 400
#define W_DIM 352
#define C_OUT_DIM 128
#define EPSVAL 1e-3f

// Fused grid: period-4 interleave, 3 zero-role + 1 compute-role blocks.
// (Exact R12 proven structure/body: best measured fused = 118.8us.)
#define NB_TOTAL 12000
#define N_ZERO_BLK 9000
#define ZERO_THREADS (N_ZERO_BLK * 256)

// Voxel-wise results staged here (fully overwritten each launch).
__device__ float g_vox[K_VOX * C_OUT_DIM];   // 6.1 MB

// 16B vector reduction (sm_90+): one REDG op instead of four.
__device__ __forceinline__ void red_add_v4(float* dst, float4 v) {
    asm volatile("red.global.add.v4.f32 [%0], {%1, %2, %3, %4};"
                 :: "l"(dst), "f"(v.x), "f"(v.y), "f"(v.z), "f"(v.w)
                 : "memory");
}

// ---------------------------------------------------------------------------
// Fused kernel: zero the 720MB output AND compute voxel features concurrently
// as interleaved blocks of one grid (proven overlap mechanism; 3:1 ratio).
// ---------------------------------------------------------------------------
__global__ __launch_bounds__(256) void fused_kernel(
    const float* __restrict__ feat,     // [K, T, F]
    const float* __restrict__ w1,       // [F, 16]
    const float* __restrict__ b1,
    const float* __restrict__ gamma1, const float* __restrict__ beta1,
    const float* __restrict__ mean1,  const float* __restrict__ var1,
    const float* __restrict__ w2,       // [32, 64]
    const float* __restrict__ b2,
    const float* __restrict__ gamma2, const float* __restrict__ beta2,
    const float* __restrict__ mean2,  const float* __restrict__ var2,
    float*       __restrict__ out,      // [1, D, H, W, 128] — zeroed here
    int n4)                             // out_size / 4 (float4 count)
{
    const int bid = blockIdx.x;
    const int tid = threadIdx.x;
    const int r = bid & 3;

    if (r < 3) {
        // ---------------- Zero role ----------------
        const int zid = (bid >> 2) * 3 + r;
        float4* o4 = (float4*)out;
        const float4 z = make_float4(0.f, 0.f, 0.f, 0.f);
        for (int i = zid * 256 + tid; i < n4; i += ZERO_THREADS) o4[i] = z;
        return;
    }

    // ---------------- Compute role ----------------
    const int cid = bid >> 2;                   // 0..2999
    const int g   = tid >> 6;                   // group 0..3 (one voxel each)
    const int v   = tid & 63;                   // output channel within group
    const int k   = cid * 4 + g;                // voxel id

    __shared__ float sw1[F_IN * 16];
    __shared__ float sb1[16], ss1[16], so1[16], spw1b[16];
    __shared__ float sfeat[4][T_PTS * F_IN];
    __shared__ int   smask[4][T_PTS];
    __shared__ __align__(16) float pw1s[4][T_PTS * 16];
    __shared__ float sagg1[4][16];

    // Block-invariant stage-1 params
    if (tid < F_IN * 16) sw1[tid] = w1[tid];
    if (tid < 16) {
        float s = gamma1[tid] * rsqrtf(var1[tid] + EPSVAL);
        float o = beta1[tid] - mean1[tid] * s;
        float bb = b1[tid];
        ss1[tid] = s; so1[tid] = o; sb1[tid] = bb;
        spw1b[tid] = fmaxf(bb, 0.f) * s + o;    // pw1 of a fully-masked point
    }

    // Per-thread stage-2 params (thread owns channels v and 64+v)
    const float s2v = gamma2[v] * rsqrtf(var2[v] + EPSVAL);
    const float o2v = beta2[v] - mean2[v] * s2v;
    const float b2v = b2[v];
    const float pw2b = fmaxf(b2v, 0.f) * s2v + o2v;   // pw2 of a masked point

    float w2A[16], w2B[16];
#pragma unroll
    for (int j = 0; j < 16; j++) {
        w2A[j] = __ldg(&w2[j * 64 + v]);
        w2B[j] = __ldg(&w2[(16 + j) * 64 + v]);
    }

    // Load this group's point features
    for (int i = v; i < T_PTS * F_IN; i += 64)
        sfeat[g][i] = feat[k * (T_PTS * F_IN) + i];
    __syncthreads();

    // Mask: point valid iff max over its features != 0
    if (v < T_PTS) {
        float m = sfeat[g][v * F_IN];
#pragma unroll
        for (int f = 1; f < F_IN; f++) m = fmaxf(m, sfeat[g][v * F_IN + f]);
        smask[g][v] = (m != 0.f) ? 1 : 0;
    }
    __syncthreads();

    // Stage 1: pw1_eff[t][u] (masked rows take the constant pw1b[u])
    for (int e = v; e < T_PTS * 16; e += 64) {
        const int t = e >> 4, u = e & 15;
        float val;
        if (smask[g][t]) {
            float d = sb1[u];
#pragma unroll
            for (int f = 0; f < F_IN; f++)
                d = fmaf(sfeat[g][t * F_IN + f], sw1[f * 16 + u], d);
            val = fmaxf(d, 0.f) * ss1[u] + so1[u];
        } else {
            val = spw1b[u];
        }
        pw1s[g][e] = val;
    }
    __syncthreads();

    // agg1[u] = max over ALL t of pw1_eff (reference maxes pre-mask)
    if (v < 16) {
        float m = pw1s[g][v];
        for (int t = 1; t < T_PTS; t++) m = fmaxf(m, pw1s[g][t * 16 + v]);
        sagg1[g][v] = m;
    }
    __syncthreads();

    // Stage 2: per-channel dot over valid rows
    float aggdot = 0.f;
#pragma unroll
    for (int j = 0; j < 16; j++) aggdot = fmaf(sagg1[g][j], w2B[j], aggdot);
    const float base2 = b2v + aggdot;

    float vmax = -3.4e38f, amax = -3.4e38f;
    int anyInvalid = 0, anyValid = 0;
    for (int t = 0; t < T_PTS; t++) {
        if (smask[g][t]) {
            anyValid = 1;
            const float4* row = (const float4*)(pw1s[g] + t * 16);
            float4 r0 = row[0], r1 = row[1], r2 = row[2], r3 = row[3];
            float d0 = base2, d1 = 0.f;
            d0 = fmaf(r0.x, w2A[0], d0);  d1 = fmaf(r0.y, w2A[1], d1);
            d0 = fmaf(r0.z, w2A[2], d0);  d1 = fmaf(r0.w, w2A[3], d1);
            d0 = fmaf(r1.x, w2A[4], d0);  d1 = fmaf(r1.y, w2A[5], d1);
            d0 = fmaf(r1.z, w2A[6], d0);  d1 = fmaf(r1.w, w2A[7], d1);
            d0 = fmaf(r2.x, w2A[8], d0);  d1 = fmaf(r2.y, w2A[9], d1);
            d0 = fmaf(r2.z, w2A[10], d0); d1 = fmaf(r2.w, w2A[11], d1);
            d0 = fmaf(r3.x, w2A[12], d0); d1 = fmaf(r3.y, w2A[13], d1);
            d0 = fmaf(r3.z, w2A[14], d0); d1 = fmaf(r3.w, w2A[15], d1);
            float pw2 = fmaxf(d0 + d1, 0.f) * s2v + o2v;
            vmax = fmaxf(vmax, pw2);
            amax = fmaxf(amax, pw2);
        } else {
            anyInvalid = 1;
        }
    }

    float outA, outB;
    if (!anyValid) {
        outA = 0.f; outB = 0.f;
    } else if (anyInvalid) {
        amax = fmaxf(amax, pw2b);
        outA = fmaxf(vmax, 0.f);
        outB = fmaxf(amax, 0.f);
    } else {
        outA = vmax; outB = amax;
    }

    g_vox[k * C_OUT_DIM + v]      = outA;
    g_vox[k * C_OUT_DIM + 64 + v] = outB;
}

// ---------------------------------------------------------------------------
// Scatter: vectorized reductions (red.global.add.v4.f32) with MLP=2.
// 750 blocks x 256 threads; each thread handles two independent float4s
// (load both upfront, then two 16B reductions).
// Total REDG warp-ops: 48K (4x fewer than scalar atomicAdd).
// ---------------------------------------------------------------------------
__global__ __launch_bounds__(256) void scatter_kernel(
    const int* __restrict__ coord,      // [K, 4]
    float*     __restrict__ out)
{
    const int i0 = blockIdx.x * 512 + threadIdx.x;   // 0 .. K*32-1 (two halves)
    const int i1 = i0 + 256;

    const int k0 = i0 >> 5, c40 = i0 & 31;
    const int k1 = i1 >> 5, c41 = i1 & 31;

    // Issue all loads before any reduction (MLP).
    const int4 cc0 = __ldg(&((const int4*)coord)[k0]);
    const int4 cc1 = __ldg(&((const int4*)coord)[k1]);
    const float4 v0 = ((const float4*)(g_vox + k0 * C_OUT_DIM))[c40];
    const float4 v1 = ((const float4*)(g_vox + k1 * C_OUT_DIM))[c41];

    const int base0 =
        (((cc0.x * D_DIM + cc0.y) * H_DIM + cc0.z) * W_DIM + cc0.w) * C_OUT_DIM;
    const int base1 =
        (((cc1.x * D_DIM + cc1.y) * H_DIM + cc1.z) * W_DIM + cc1.w) * C_OUT_DIM;

    red_add_v4(out + base0 + c40 * 4, v0);
    red_add_v4(out + base1 + c41 * 4, v1);
}

// ---------------------------------------------------------------------------
extern "C" void kernel_launch(void* const* d_in, const int* in_sizes, int n_in,
                              void* d_out, int out_size) {
    const float* feat   = (const float*)d_in[0];
    const float* w1     = (const float*)d_in[1];
    const float* b1     = (const float*)d_in[2];
    const float* gamma1 = (const float*)d_in[3];
    const float* beta1  = (const float*)d_in[4];
    const float* mean1  = (const float*)d_in[5];
    const float* var1   = (const float*)d_in[6];
    const float* w2     = (const float*)d_in[7];
    const float* b2     = (const float*)d_in[8];
    const float* gamma2 = (const float*)d_in[9];
    const float* beta2  = (const float*)d_in[10];
    const float* mean2  = (const float*)d_in[11];
    const float* var2   = (const float*)d_in[12];
    const int*   coord  = (const int*)d_in[13];
    float* out = (float*)d_out;

    const int n4 = out_size / 4;
    fused_kernel<<<NB_TOTAL, 256>>>(feat, w1, b1, gamma1, beta1, mean1, var1,
                                    w2, b2, gamma2, beta2, mean2, var2,
                                    out, n4);
    scatter_kernel<<<(K_VOX * 32) / 512, 256>>>(coord, out);
}

// round 16
// speedup vs baseline: 1.4773x; 1.4773x over previous
#include <cuda_runtime.h>

// Problem constants (match reference)
#define K_VOX 12000
#define T_PTS 35
#define F_IN  7
#define D_DIM 10
#define H_DIM 400
#define W_DIM 352
#define C_OUT_DIM 128
#define EPSVAL 1e-3f

// Fused grid: period-10 interleave, 7 zero-role + 3 compute-role blocks.
// fc = 0.3 — the predicted crossing of compute-span and zero-span curves.
#define NB_TOTAL 10000
#define N_ZERO_BLK 7000
#define ZERO_THREADS (N_ZERO_BLK * 256)

// Voxel-wise results staged here (fully overwritten each launch).
__device__ float g_vox[K_VOX * C_OUT_DIM];   // 6.1 MB

// 16B vector reduction (sm_90+): one REDG op instead of four.
__device__ __forceinline__ void red_add_v4(float* dst, float4 v) {
    asm volatile("red.global.add.v4.f32 [%0], {%1, %2, %3, %4};"
                 :: "l"(dst), "f"(v.x), "f"(v.y), "f"(v.z), "f"(v.w)
                 : "memory");
}

// ---------------------------------------------------------------------------
// Fused kernel: zero the 720MB output AND compute voxel features concurrently
// as interleaved blocks of one grid (proven overlap mechanism; 7:3 ratio).
// ---------------------------------------------------------------------------
__global__ __launch_bounds__(256) void fused_kernel(
    const float* __restrict__ feat,     // [K, T, F]
    const float* __restrict__ w1,       // [F, 16]
    const float* __restrict__ b1,
    const float* __restrict__ gamma1, const float* __restrict__ beta1,
    const float* __restrict__ mean1,  const float* __restrict__ var1,
    const float* __restrict__ w2,       // [32, 64]
    const float* __restrict__ b2,
    const float* __restrict__ gamma2, const float* __restrict__ beta2,
    const float* __restrict__ mean2,  const float* __restrict__ var2,
    float*       __restrict__ out,      // [1, D, H, W, 128] — zeroed here
    int n4)                             // out_size / 4 (float4 count)
{
    const int bid = blockIdx.x;
    const int tid = threadIdx.x;
    const int r = bid % 10;

    if (r < 7) {
        // ---------------- Zero role ----------------
        const int zid = (bid / 10) * 7 + r;
        float4* o4 = (float4*)out;
        const float4 z = make_float4(0.f, 0.f, 0.f, 0.f);
        for (int i = zid * 256 + tid; i < n4; i += ZERO_THREADS) o4[i] = z;
        return;
    }

    // ---------------- Compute role ----------------
    const int cid = (bid / 10) * 3 + (r - 7);   // 0..2999
    const int g   = tid >> 6;                   // group 0..3 (one voxel each)
    const int v   = tid & 63;                   // output channel within group
    const int k   = cid * 4 + g;                // voxel id

    __shared__ float sw1[F_IN * 16];
    __shared__ float sb1[16], ss1[16], so1[16], spw1b[16];
    __shared__ float sfeat[4][T_PTS * F_IN];
    __shared__ int   smask[4][T_PTS];
    __shared__ __align__(16) float pw1s[4][T_PTS * 16];
    __shared__ float sagg1[4][16];

    // Block-invariant stage-1 params
    if (tid < F_IN * 16) sw1[tid] = w1[tid];
    if (tid < 16) {
        float s = gamma1[tid] * rsqrtf(var1[tid] + EPSVAL);
        float o = beta1[tid] - mean1[tid] * s;
        float bb = b1[tid];
        ss1[tid] = s; so1[tid] = o; sb1[tid] = bb;
        spw1b[tid] = fmaxf(bb, 0.f) * s + o;    // pw1 of a fully-masked point
    }

    // Per-thread stage-2 params (thread owns channels v and 64+v)
    const float s2v = gamma2[v] * rsqrtf(var2[v] + EPSVAL);
    const float o2v = beta2[v] - mean2[v] * s2v;
    const float b2v = b2[v];
    const float pw2b = fmaxf(b2v, 0.f) * s2v + o2v;   // pw2 of a masked point

    float w2A[16], w2B[16];
#pragma unroll
    for (int j = 0; j < 16; j++) {
        w2A[j] = __ldg(&w2[j * 64 + v]);
        w2B[j] = __ldg(&w2[(16 + j) * 64 + v]);
    }

    // Load this group's point features
    for (int i = v; i < T_PTS * F_IN; i += 64)
        sfeat[g][i] = feat[k * (T_PTS * F_IN) + i];
    __syncthreads();

    // Mask: point valid iff max over its features != 0
    if (v < T_PTS) {
        float m = sfeat[g][v * F_IN];
#pragma unroll
        for (int f = 1; f < F_IN; f++) m = fmaxf(m, sfeat[g][v * F_IN + f]);
        smask[g][v] = (m != 0.f) ? 1 : 0;
    }
    __syncthreads();

    // Stage 1: pw1_eff[t][u] (masked rows take the constant pw1b[u])
    for (int e = v; e < T_PTS * 16; e += 64) {
        const int t = e >> 4, u = e & 15;
        float val;
        if (smask[g][t]) {
            float d = sb1[u];
#pragma unroll
            for (int f = 0; f < F_IN; f++)
                d = fmaf(sfeat[g][t * F_IN + f], sw1[f * 16 + u], d);
            val = fmaxf(d, 0.f) * ss1[u] + so1[u];
        } else {
            val = spw1b[u];
        }
        pw1s[g][e] = val;
    }
    __syncthreads();

    // agg1[u] = max over ALL t of pw1_eff (reference maxes pre-mask)
    if (v < 16) {
        float m = pw1s[g][v];
        for (int t = 1; t < T_PTS; t++) m = fmaxf(m, pw1s[g][t * 16 + v]);
        sagg1[g][v] = m;
    }
    __syncthreads();

    // Stage 2: per-channel dot over valid rows
    float aggdot = 0.f;
#pragma unroll
    for (int j = 0; j < 16; j++) aggdot = fmaf(sagg1[g][j], w2B[j], aggdot);
    const float base2 = b2v + aggdot;

    float vmax = -3.4e38f, amax = -3.4e38f;
    int anyInvalid = 0, anyValid = 0;
    for (int t = 0; t < T_PTS; t++) {
        if (smask[g][t]) {
            anyValid = 1;
            const float4* row = (const float4*)(pw1s[g] + t * 16);
            float4 r0 = row[0], r1 = row[1], r2 = row[2], r3 = row[3];
            float d0 = base2, d1 = 0.f;
            d0 = fmaf(r0.x, w2A[0], d0);  d1 = fmaf(r0.y, w2A[1], d1);
            d0 = fmaf(r0.z, w2A[2], d0);  d1 = fmaf(r0.w, w2A[3], d1);
            d0 = fmaf(r1.x, w2A[4], d0);  d1 = fmaf(r1.y, w2A[5], d1);
            d0 = fmaf(r1.z, w2A[6], d0);  d1 = fmaf(r1.w, w2A[7], d1);
            d0 = fmaf(r2.x, w2A[8], d0);  d1 = fmaf(r2.y, w2A[9], d1);
            d0 = fmaf(r2.z, w2A[10], d0); d1 = fmaf(r2.w, w2A[11], d1);
            d0 = fmaf(r3.x, w2A[12], d0); d1 = fmaf(r3.y, w2A[13], d1);
            d0 = fmaf(r3.z, w2A[14], d0); d1 = fmaf(r3.w, w2A[15], d1);
            float pw2 = fmaxf(d0 + d1, 0.f) * s2v + o2v;
            vmax = fmaxf(vmax, pw2);
            amax = fmaxf(amax, pw2);
        } else {
            anyInvalid = 1;
        }
    }

    float outA, outB;
    if (!anyValid) {
        outA = 0.f; outB = 0.f;
    } else if (anyInvalid) {
        amax = fmaxf(amax, pw2b);
        outA = fmaxf(vmax, 0.f);
        outB = fmaxf(amax, 0.f);
    } else {
        outA = vmax; outB = amax;
    }

    g_vox[k * C_OUT_DIM + v]      = outA;
    g_vox[k * C_OUT_DIM + 64 + v] = outB;
}

// ---------------------------------------------------------------------------
// Scatter: vectorized reductions (red.global.add.v4.f32) with MLP=2.
// Measured 7.26us in R15.
// ---------------------------------------------------------------------------
__global__ __launch_bounds__(256) void scatter_kernel(
    const int* __restrict__ coord,      // [K, 4]
    float*     __restrict__ out)
{
    const int i0 = blockIdx.x * 512 + threadIdx.x;   // two halves per block
    const int i1 = i0 + 256;

    const int k0 = i0 >> 5, c40 = i0 & 31;
    const int k1 = i1 >> 5, c41 = i1 & 31;

    // Issue all loads before any reduction (MLP).
    const int4 cc0 = __ldg(&((const int4*)coord)[k0]);
    const int4 cc1 = __ldg(&((const int4*)coord)[k1]);
    const float4 v0 = ((const float4*)(g_vox + k0 * C_OUT_DIM))[c40];
    const float4 v1 = ((const float4*)(g_vox + k1 * C_OUT_DIM))[c41];

    const int base0 =
        (((cc0.x * D_DIM + cc0.y) * H_DIM + cc0.z) * W_DIM + cc0.w) * C_OUT_DIM;
    const int base1 =
        (((cc1.x * D_DIM + cc1.y) * H_DIM + cc1.z) * W_DIM + cc1.w) * C_OUT_DIM;

    red_add_v4(out + base0 + c40 * 4, v0);
    red_add_v4(out + base1 + c41 * 4, v1);
}

// ---------------------------------------------------------------------------
extern "C" void kernel_launch(void* const* d_in, const int* in_sizes, int n_in,
                              void* d_out, int out_size) {
    const float* feat   = (const float*)d_in[0];
    const float* w1     = (const float*)d_in[1];
    const float* b1     = (const float*)d_in[2];
    const float* gamma1 = (const float*)d_in[3];
    const float* beta1  = (const float*)d_in[4];
    const float* mean1  = (const float*)d_in[5];
    const float* var1   = (const float*)d_in[6];
    const float* w2     = (const float*)d_in[7];
    const float* b2     = (const float*)d_in[8];
    const float* gamma2 = (const float*)d_in[9];
    const float* beta2  = (const float*)d_in[10];
    const float* mean2  = (const float*)d_in[11];
    const float* var2   = (const float*)d_in[12];
    const int*   coord  = (const int*)d_in[13];
    float* out = (float*)d_out;

    const int n4 = out_size / 4;
    fused_kernel<<<NB_TOTAL, 256>>>(feat, w1, b1, gamma1, beta1, mean1, var1,
                                    w2, b2, gamma2, beta2, mean2, var2,
                                    out, n4);
    scatter_kernel<<<(K_VOX * 32) / 512, 256>>>(coord, out);
}